// round 16
// baseline (speedup 1.0000x reference)
#include <cuda_runtime.h>
#include <cstdint>
#include <math.h>

// ModSTDP: bit-exact replay of JAX threefry2x32 (partitionable scheme) STDP update.
// weight shape (R,C,COUT,CIN,KH,KW) = (16,16,64,16,8,8) -> 16,777,216 f32 elements.
// STRIDE=0 => bx depends only on (ci,kh,kw) [1024 vals]; by on (o,r,c): one value
// per 1024-element block.
//
// R16: pipe-balance the threefry round. Half the rotations computed on the
// fma pipe via 64-bit wide multiply (x*2^r -> lo=x<<r, hi=x>>(32-r)), with the
// following XOR fused into one 3-input LOP3: x1' = (lo|hi)^x0'. Converted
// round = 2 fma + 1 alu; SHF round = 1 fma + 2 alu; alternating gives
// 1.5/1.5 per round (was 2 alu). alu/threefry: 40 -> 30.
// Plumbing identical to R15 (warp-local compaction, best at 79.9us).

#define N_ELEMS   16777216
#define XTAB_N    1024     // CIN*KH*KW
#define NBLK      16384    // blocks (1024 elements each)
#define WSLOTS    64       // per-warp survivor slots (lambda~28, +6.8 sigma)

__device__ uint8_t g_xtab[XTAB_N];

struct Params {
    uint32_t k0[5], k1[5], ks2[5];                // subkeys + precomputed ks2
    uint32_t c1[5], c2[5], c3[5], c4[5], c5[5];   // ks2+1, k0+2, k1+3, ks2+4, k0+5
    uint32_t Tsearch9, Tcap9, Tback9, Tminus9, Tumin9;  // thresholds << 9
    uint32_t TF9[16];                             // [0..7]=F_minus<<9, [8..15]=F_plus<<9
    uint32_t one;                                 // runtime 1 (opaque to ptxas) for mad.lo
};

// add on the IMAD (fma) pipe: a*one + b with one==1 at runtime
__device__ __forceinline__ uint32_t addI(uint32_t a, uint32_t one, uint32_t b) {
    uint32_t r;
    asm("mad.lo.u32 %0, %1, %2, %3;" : "=r"(r) : "r"(a), "r"(one), "r"(b));
    return r;
}

// Threefry-2x32, 20 rounds, key-schedule constants supplied.
// Alternating rotate implementations:
//  TFR_S: SHF rotate (1 fma + 2 alu)
//  TFR_W: wide-mul rotate, XOR fused into one LOP3 (2 fma + 1 alu)
__device__ __forceinline__ void tf2x32_pre(uint32_t k0, uint32_t k1, uint32_t ks2,
                                           uint32_t c1, uint32_t c2, uint32_t c3,
                                           uint32_t c4, uint32_t c5,
                                           uint32_t idx, uint32_t one,
                                           uint32_t& o0, uint32_t& o1) {
    uint32_t x0 = k0;                 // 0 + k0
    uint32_t x1 = addI(idx, one, k1);
#define TFR_S(r) { x0 = addI(x0, one, x1); x1 = __funnelshift_l(x1, x1, r); x1 ^= x0; }
#define TFR_W(r) { uint64_t wv = (uint64_t)x1 * (uint64_t)(1u << (r)); \
                   x0 = addI(x0, one, x1); \
                   x1 = ((uint32_t)wv | (uint32_t)(wv >> 32)) ^ x0; }
    TFR_S(13) TFR_W(15) TFR_S(26) TFR_W(6)
    x0 = addI(x0, one, k1);  x1 = addI(x1, one, c1);
    TFR_S(17) TFR_W(29) TFR_S(16) TFR_W(24)
    x0 = addI(x0, one, ks2); x1 = addI(x1, one, c2);
    TFR_S(13) TFR_W(15) TFR_S(26) TFR_W(6)
    x0 = addI(x0, one, k0);  x1 = addI(x1, one, c3);
    TFR_S(17) TFR_W(29) TFR_S(16) TFR_W(24)
    x0 = addI(x0, one, k1);  x1 = addI(x1, one, c4);
    TFR_S(13) TFR_W(15) TFR_S(26) TFR_W(6)
    x0 = addI(x0, one, ks2); x1 = addI(x1, one, c5);
#undef TFR_S
#undef TFR_W
    o0 = x0; o1 = x1;
}

// Host variant for subkey derivation
static inline void tf2x32_host(uint32_t k0, uint32_t k1,
                               uint32_t x0, uint32_t x1,
                               uint32_t& o0, uint32_t& o1) {
    auto rot = [](uint32_t x, int r) { return (x << r) | (x >> (32 - r)); };
    uint32_t ks2 = k0 ^ k1 ^ 0x1BD11BDAu;
    x0 += k0; x1 += k1;
#define TFRH(r) { x0 += x1; x1 = rot(x1, r); x1 ^= x0; }
    TFRH(13) TFRH(15) TFRH(26) TFRH(6)   x0 += k1;  x1 += ks2 + 1u;
    TFRH(17) TFRH(29) TFRH(16) TFRH(24)  x0 += ks2; x1 += k0  + 2u;
    TFRH(13) TFRH(15) TFRH(26) TFRH(6)   x0 += k0;  x1 += k1  + 3u;
    TFRH(17) TFRH(29) TFRH(16) TFRH(24)  x0 += k1;  x1 += ks2 + 4u;
    TFRH(13) TFRH(15) TFRH(26) TFRH(6)   x0 += ks2; x1 += k0  + 5u;
#undef TFRH
    o0 = x0; o1 = x1;
}

// prep: xtab only (x_times = 7 - sum_t input_spikes), 1024 entries
__global__ void __launch_bounds__(256) prep_kernel(const int* __restrict__ inS) {
    int u = blockIdx.x * 256 + threadIdx.x;
    if (u < XTAB_N) {
        int s = 0;
#pragma unroll
        for (int tt = 0; tt < 7; ++tt) s += inS[tt * XTAB_N + u];
        g_xtab[u] = (uint8_t)(7 - s);
    }
}

// Fused kernel: 128 threads x 8 elements = 1024 elements = one (r,c,o) group.
__global__ void __launch_bounds__(128, 12) stdp_fused(const float* __restrict__ w,
                                                      const int* __restrict__ outS,
                                                      float* __restrict__ out,
                                                      Params P) {
    __shared__ uint4    sL[8];              // per-bx: {Tg9|plus, kg0, kg1, ks2}
    __shared__ uint4    sLc[8];             // per-bx: {c1, c2, c3, c4}
    __shared__ uint32_t sLc5[8];            // per-bx: c5
    __shared__ uint32_t sTF9[16];
    __shared__ uint32_t s_list[4][WSLOTS];  // per-warp survivors: le | plus<<10

    uint32_t tid = threadIdx.x, lane = tid & 31u, wid = tid >> 5, blk = blockIdx.x;
    if (tid < 16) sTF9[tid] = P.TF9[tid];
    if (tid < 8) {
        // by for this block: y_times = 7 - sum_t outS[t][o*256+r*16+c]
        uint32_t o = blk & 63u, c = (blk >> 6) & 15u, r = (blk >> 10) & 15u;
        uint32_t ypos = o * 256u + r * 16u + c;
        int s = 0;
#pragma unroll
        for (int tt = 0; tt < 7; ++tt) s += outS[tt * 16384 + ypos];
        uint32_t by = (uint32_t)(7 - s);
        bool B = (by == 7u);
        uint32_t bx = tid;
        bool A = (bx == 7u);
        bool plus = !A && (B || bx <= by);
        uint32_t Tg9 = plus ? (B ? P.Tsearch9 : P.Tcap9)
                            : (A ? (B ? 0u : P.Tback9) : P.Tminus9);
        int ks = plus ? 0 : 1;
        // Tg9 is a multiple of 512 -> bit 0 carries the plus flag; the gate
        // compare uses (v|1) < (Tg9|plus), exact for even Tg9.
        sL[bx]   = make_uint4(Tg9 | (plus ? 1u : 0u), P.k0[ks], P.k1[ks], P.ks2[ks]);
        sLc[bx]  = make_uint4(P.c1[ks], P.c2[ks], P.c3[ks], P.c4[ks]);
        sLc5[bx] = P.c5[ks];
    }
    __syncthreads();

    uint32_t i0 = blk * 1024u + tid * 8u;
    uint32_t khkw = i0 & 63u, ci = (i0 >> 6) & 15u;
    uint2 xw = *reinterpret_cast<const uint2*>(&g_xtab[ci * 64u + khkw]); // 8 bx bytes

    // pass-through copy now; this warp's survivors patch out[] with scattered
    // stores after __syncwarp below (warp-scoped ordering suffices: survivors
    // belong to this warp's own 256 elements).
    {
        float4 w0 = *reinterpret_cast<const float4*>(w + i0);
        float4 w1 = *reinterpret_cast<const float4*>(w + i0 + 4);
        *reinterpret_cast<float4*>(out + i0)     = w0;
        *reinterpret_cast<float4*>(out + i0 + 4) = w1;
    }

    // ---- gate: 8 independent threefry chains, results packed into fireMask ----
    uint32_t fireMask = 0u;
#pragma unroll
    for (int e = 0; e < 8; ++e) {
        uint32_t word = (e < 4) ? xw.x : xw.y;
        uint32_t bx = __byte_perm(word, 0u, 0x4440u | (uint32_t)(e & 3));
        uint4 L  = sL[bx];
        uint4 Lc = sLc[bx];
        uint32_t c5 = sLc5[bx];
        uint32_t a, b;
        tf2x32_pre(L.y, L.z, L.w, Lc.x, Lc.y, Lc.z, Lc.w, c5,
                   i0 + (uint32_t)e, P.one, a, b);
        uint32_t m = (a ^ b) | 1u;               // single LOP3
        if (m < L.x) fireMask |= (1u << e);
    }

    // ---- warp-local compaction: shfl inclusive scan, no atomics ----
    uint32_t nf = (uint32_t)__popc(fireMask);
    uint32_t incl = nf;
#pragma unroll
    for (int d = 1; d < 32; d <<= 1) {
        uint32_t v = __shfl_up_sync(0xFFFFFFFFu, incl, d);
        if (lane >= (uint32_t)d) incl += v;
    }
    uint32_t n_w = __shfl_sync(0xFFFFFFFFu, incl, 31);   // warp survivor count

    uint32_t pos = incl - nf;
    uint32_t le0 = tid * 8u;
#pragma unroll
    for (int e = 0; e < 8; ++e) {
        if ((fireMask >> e) & 1u) {
            uint32_t word = (e < 4) ? xw.x : xw.y;
            uint32_t bx = __byte_perm(word, 0u, 0x4440u | (uint32_t)(e & 3));
            uint32_t plus = sL[bx].x & 1u;       // re-derive (rare path)
            if (pos < WSLOTS)
                s_list[wid][pos] = (le0 + (uint32_t)e) | (plus << 10);
            pos++;
        }
    }
    __syncwarp();   // orders pass-through stores + s_list writes within the warp

    // ---- survivor stage (warp-local): 2 draws each, scattered 4B patch stores ----
    uint32_t n = min(n_w, (uint32_t)WSLOTS);
    for (uint32_t t = lane; t < n; t += 32u) {
        uint32_t entry = s_list[wid][t];
        uint32_t le   = entry & 1023u;
        bool     plus = (entry >> 10) & 1u;
        uint32_t gidx = blk * 1024u + le;

        int wi = (int)w[gidx];                   // L1-hot (warp just read it)
        bool noop = plus ? (wi == 7) : (wi == 0);   // clamp-identity
        if (!noop) {
            int ks = plus ? 3 : 2;
            uint32_t a, b;
            tf2x32_pre(P.k0[ks], P.k1[ks], P.ks2[ks],
                       P.c1[ks], P.c2[ks], P.c3[ks], P.c4[ks], P.c5[ks],
                       gidx, P.one, a, b);
            uint32_t abf = a ^ b;
            tf2x32_pre(P.k0[4], P.k1[4], P.ks2[4],
                       P.c1[4], P.c2[4], P.c3[4], P.c4[4], P.c5[4],
                       gidx, P.one, a, b);
            uint32_t abu = a ^ b;
            uint32_t TF9 = sTF9[(plus ? 8 : 0) + wi];
            if ((abf < TF9) || (abu < P.Tumin9)) {
                int nw = wi + (plus ? 1 : -1);   // stays in [0,7] (noop pruned)
                out[gidx] = (float)nw;
            }
        }
    }
}

static inline uint32_t thresh_from_prob(float p) {
    if (p <= 0.0f) return 0u;
    double v = ceil((double)p * 8388608.0);      // 2^23; u=m*2^-23 exactly
    if (v < 0.0) return 0u;
    if (v > 4294967295.0) return 0xFFFFFFFFu;
    return (uint32_t)v;
}

static inline uint32_t shl9_clamp(uint32_t T) {
    uint64_t v = (uint64_t)T << 9;               // m<T <=> (o0^o1) < (T<<9)
    return v > 0xFFFFFFFFull ? 0xFFFFFFFFu : (uint32_t)v;
}

extern "C" void kernel_launch(void* const* d_in, const int* in_sizes, int n_in,
                              void* d_out, int out_size) {
    const float* w    = (const float*)d_in[0];
    const int*   inS  = (const int*)d_in[1];
    const int*   outS = (const int*)d_in[2];

    Params P;
    for (int j = 0; j < 5; ++j) {
        tf2x32_host(0u, 42u, 0u, (uint32_t)j, P.k0[j], P.k1[j]);
        P.ks2[j] = P.k0[j] ^ P.k1[j] ^ 0x1BD11BDAu;
        P.c1[j] = P.ks2[j] + 1u;
        P.c2[j] = P.k0[j]  + 2u;
        P.c3[j] = P.k1[j]  + 3u;
        P.c4[j] = P.ks2[j] + 4u;
        P.c5[j] = P.k0[j]  + 5u;
    }

    P.Tcap9    = shl9_clamp(thresh_from_prob((float)0.102));
    P.Tminus9  = shl9_clamp(thresh_from_prob((float)0.051));
    P.Tsearch9 = shl9_clamp(thresh_from_prob((float)0.032));
    P.Tback9   = shl9_clamp(thresh_from_prob((float)0.96));
    P.Tumin9   = shl9_clamp(thresh_from_prob((float)0.008));

    const float inv7 = (float)(1.0 / 7.0);
    for (int ww = 0; ww < 8; ++ww) {
        float rr = (float)ww * inv7;
        float a  = (1.0f - rr) * (1.0f + rr);    // F_minus prob
        float b  = rr * (2.0f - rr);             // F_plus prob
        P.TF9[ww]     = shl9_clamp(thresh_from_prob(a));
        P.TF9[8 + ww] = shl9_clamp(thresh_from_prob(b));
    }
    P.one = 1u;

    prep_kernel<<<(XTAB_N + 255) / 256, 256>>>(inS);
    stdp_fused<<<NBLK, 128>>>(w, outS, (float*)d_out, P);
}